// round 1
// baseline (speedup 1.0000x reference)
#include <cuda_runtime.h>
#include <cstdint>

#define NF 32
#define NPOLY 6545
#define BATCH 8192
#define ROWS_PER_BLOCK 32
#define NCHUNK 8
#define THREADS (32 * NCHUNK)
#define TILE_P 32
#define XS_BYTES (32 * 33 * 4)                       /* 4224  */
#define WBUF_BYTES (NCHUNK * 2 * TILE_P * NF * 4)    /* 65536 */
#define SMEM_BYTES (XS_BYTES + WBUF_BYTES)           /* 69760 */

// ---------- PTX helpers ----------
__device__ __forceinline__ void cp16(uint32_t dst, const float* src) {
    unsigned long long g;
    asm volatile("cvta.to.global.u64 %0, %1;" : "=l"(g) : "l"(src));
    asm volatile("cp.async.cg.shared.global [%0], [%1], 16;" :: "r"(dst), "l"(g));
}
__device__ __forceinline__ void cp_commit() {
    asm volatile("cp.async.commit_group;" ::: "memory");
}
__device__ __forceinline__ void cp_wait0() {
    asm volatile("cp.async.wait_group 0;" ::: "memory");
}
__device__ __forceinline__ unsigned long long pack2(float f) {
    unsigned long long r;
    asm("mov.b64 %0, {%1, %1};" : "=l"(r) : "f"(f));
    return r;
}
#define FMA2(a, w, f) asm("fma.rn.f32x2 %0, %1, %2, %0;" : "+l"(a) : "l"(w), "l"(f))

// cubic-level chunk boundaries on f (balanced by comb(F+2,3) cumulative work)
__constant__ int c_Flo[NCHUNK] = { 0, 11, 18, 22, 25, 27, 29, 31};
__constant__ int c_Fhi[NCHUNK] = {11, 18, 22, 25, 27, 29, 31, 32};

// Load one 32-row x 32-col fp32 W tile (4 KB) into smem, warp-cooperative.
// Rows past the end of W are clamped (values never consumed).
__device__ __forceinline__ void load_tile(uint32_t dsts, const float* __restrict__ W,
                                          int row0, int lane) {
#pragma unroll
    for (int i = 0; i < 8; i++) {
        int e = i * 32 + lane;               // 16-byte unit index 0..255
        int r = row0 + (e >> 3);
        if (r > NPOLY - 1) r = NPOLY - 1;
        cp16(dsts + (uint32_t)e * 16u, W + (size_t)r * NF + (e & 7) * 4);
    }
    cp_commit();
}

// One feature step: (maybe refill W tile), then 32 packed FMAs against W row.
#define STEP(FEAT)                                                              \
    do {                                                                        \
        if ((tc & (TILE_P - 1)) == 0) {                                         \
            cp_wait0();                                                         \
            __syncwarp();                                                       \
            wcur = parity ? bufB : bufA;                                        \
            if (next_row < pend) {                                              \
                load_tile(parity ? sA : sB, W, next_row, lane);                 \
                next_row += TILE_P;                                             \
            }                                                                   \
            parity ^= 1;                                                        \
        }                                                                       \
        {                                                                       \
            const ulonglong2* wr =                                              \
                (const ulonglong2*)(wcur + (tc & (TILE_P - 1)) * (NF * 4));     \
            unsigned long long f2_ = pack2(FEAT);                               \
            ulonglong2 q0 = wr[0], q1 = wr[1], q2 = wr[2], q3 = wr[3];          \
            ulonglong2 q4 = wr[4], q5 = wr[5], q6 = wr[6], q7 = wr[7];          \
            FMA2(acc[0],  q0.x, f2_); FMA2(acc[1],  q0.y, f2_);                 \
            FMA2(acc[2],  q1.x, f2_); FMA2(acc[3],  q1.y, f2_);                 \
            FMA2(acc[4],  q2.x, f2_); FMA2(acc[5],  q2.y, f2_);                 \
            FMA2(acc[6],  q3.x, f2_); FMA2(acc[7],  q3.y, f2_);                 \
            FMA2(acc[8],  q4.x, f2_); FMA2(acc[9],  q4.y, f2_);                 \
            FMA2(acc[10], q5.x, f2_); FMA2(acc[11], q5.y, f2_);                 \
            FMA2(acc[12], q6.x, f2_); FMA2(acc[13], q6.y, f2_);                 \
            FMA2(acc[14], q7.x, f2_); FMA2(acc[15], q7.y, f2_);                 \
            tc++;                                                               \
        }                                                                       \
    } while (0)

__global__ void __launch_bounds__(THREADS)
taylor_kernel(const float* __restrict__ x, const float* __restrict__ W,
              float* __restrict__ out) {
    extern __shared__ char smem[];
    float* xs = (float*)smem;             // [32][33] padded
    char* wbase = smem + XS_BYTES;        // 8 warps x 2 x 4KB double buffers

    const int tid  = threadIdx.x;
    const int lane = tid & 31;            // lane == row within tile
    const int w    = tid >> 5;            // warp == feature chunk
    const int row0 = blockIdx.x * ROWS_PER_BLOCK;

    // stage x tile (coalesced), padded stride 33 for conflict-free row reads
    for (int idx = tid; idx < 32 * 32; idx += THREADS) {
        int r = idx >> 5, c = idx & 31;
        xs[r * 33 + c] = x[(size_t)(row0 + r) * NF + c];
    }
    __syncthreads();

    const float* myx = xs + lane * 33;

    // this warp's feature range [pstart, pend) in reference monomial order
    const int flo = c_Flo[w], fhi = c_Fhi[w];
    const int nlo = flo + 2, nhi = fhi + 2;
    const int pstart = (w == 0) ? 0 : 561 + (nlo * (nlo - 1) * (nlo - 2)) / 6;
    const int pend   = 561 + (nhi * (nhi - 1) * (nhi - 2)) / 6;

    char* bufA = wbase + w * (2 * TILE_P * NF * 4);
    char* bufB = bufA + TILE_P * NF * 4;
    const uint32_t sA = (uint32_t)__cvta_generic_to_shared(bufA);
    const uint32_t sB = (uint32_t)__cvta_generic_to_shared(bufB);

    // preload first tile into A
    load_tile(sA, W, pstart, lane);
    int next_row = pstart + TILE_P;
    int parity = 0;
    const char* wcur = bufA;
    int tc = 0;

    unsigned long long acc[16];
#pragma unroll
    for (int i = 0; i < 16; i++) acc[i] = 0ULL;

    if (w == 0) {
        STEP(1.0f);                                  // p = 0 : constant term
        for (int f = 0; f < 32; f++) STEP(myx[f]);   // p = 1..32 : linear
        for (int a = 0; a < 32; a++) {               // p = 33..560 : quadratic
            float xa = myx[a];
            for (int b = 0; b <= a; b++) STEP(xa * myx[b]);
        }
    }
    // cubic: x_f * x_a * x_b with b <= a <= f, f in this warp's range
    for (int f = flo; f < fhi; f++) {
        float xf = myx[f];
        for (int a = 0; a <= f; a++) {
            float t = xf * myx[a];
            for (int b = 0; b <= a; b++) STEP(t * myx[b]);
        }
    }

    cp_wait0();          // drain any in-flight prefetch before smem overlay
    __syncthreads();     // all warps done reading their W buffers

    // per-warp partials -> smem (overlaying W buffers), padded [8][32][33]
    float* red = (float*)wbase;
#pragma unroll
    for (int i = 0; i < 16; i++) {
        float lo, hi;
        asm("mov.b64 {%0, %1}, %2;" : "=f"(lo), "=f"(hi) : "l"(acc[i]));
        red[(w * 32 + lane) * 33 + 2 * i]     = lo;
        red[(w * 32 + lane) * 33 + 2 * i + 1] = hi;
    }
    __syncthreads();

    // reduce 8 chunks + residual x, coalesced store
    for (int idx = tid; idx < 32 * 32; idx += THREADS) {
        int r = idx >> 5, c = idx & 31;
        float s = xs[r * 33 + c];
#pragma unroll
        for (int k = 0; k < NCHUNK; k++) s += red[(k * 32 + r) * 33 + c];
        out[(size_t)(row0 + r) * NF + c] = s;
    }
}

extern "C" void kernel_launch(void* const* d_in, const int* in_sizes, int n_in,
                              void* d_out, int out_size) {
    const float* x = (const float*)d_in[0];
    const float* W = (const float*)d_in[1];
    // defensive: disambiguate by element counts (x: 8192*32, W: 6545*32)
    if (n_in >= 2 && in_sizes[0] == NPOLY * NF && in_sizes[1] == BATCH * NF) {
        const float* t = x; x = W; W = t;
    }
    cudaFuncSetAttribute(taylor_kernel,
                         cudaFuncAttributeMaxDynamicSharedMemorySize, SMEM_BYTES);
    taylor_kernel<<<BATCH / ROWS_PER_BLOCK, THREADS, SMEM_BYTES>>>(
        x, W, (float*)d_out);
}